// round 11
// baseline (speedup 1.0000x reference)
#include <cuda_runtime.h>
#include <cuda_bf16.h>
#include <math.h>

#define NN_MAX 50000
#define EE_MAX 600000
#define DD 128
#define HH 4
#define CC 32
#define NEG_SLOPE 0.2f
#define LN_EPS 1e-5f
#define NB_MAX 256

// ---------------- device scratch ----------------
static __device__ float g_h[NN_MAX * DD];
static __device__ float g_asrc[NN_MAX * HH];
static __device__ float g_adst[NN_MAX * HH];
static __device__ float g_alpha[EE_MAX * HH];   // per-edge unnormalized weight
static __device__ float g_pself[NN_MAX * HH];   // self-loop weight
static __device__ float g_den[NN_MAX * HH];     // softmax denominator
static __device__ float g_wa[DD * 2 * HH];      // folded W@att: [k][src4|dst4]
static __device__ int   g_deg[NN_MAX];
static __device__ int   g_rowoff[NN_MAX];
static __device__ int   g_cursor[NN_MAX];
static __device__ int   g_srclist[EE_MAX];
static __device__ int   g_bsum[NB_MAX];
static __device__ int   g_is64;

// ---------------- f32x2 helpers ----------------
__device__ __forceinline__ unsigned long long pk2(float lo, float hi) {
    unsigned long long r;
    asm("mov.b64 %0, {%1, %2};" : "=l"(r) : "f"(lo), "f"(hi));
    return r;
}
__device__ __forceinline__ unsigned long long fma2(unsigned long long a,
                                                   unsigned long long b,
                                                   unsigned long long c) {
    unsigned long long d;
    asm("fma.rn.f32x2 %0, %1, %2, %3;" : "=l"(d) : "l"(a), "l"(b), "l"(c));
    return d;
}
__device__ __forceinline__ float2 upk2(unsigned long long v) {
    float lo, hi;
    asm("mov.b64 {%0, %1}, %2;" : "=f"(lo), "=f"(hi) : "l"(v));
    return make_float2(lo, hi);
}
__device__ __forceinline__ float lrelu(float v) {
    return (v > 0.f) ? v : v * NEG_SLOPE;
}
__device__ __forceinline__ float4 lrelu4(float4 v) {
    return make_float4(lrelu(v.x), lrelu(v.y), lrelu(v.z), lrelu(v.w));
}

// ---------------- Kernel 0: zero degrees + detect dtype ----------------
__global__ void detect_zero_kernel(const int* __restrict__ ei32, int E, int n)
{
    int i = blockIdx.x * 256 + threadIdx.x;
    if (i < n) g_deg[i] = 0;
    if (blockIdx.x == 0) {
        int checks = 2 * E; if (checks > 4096) checks = 4096;
        int nz = 0;
        for (int j = threadIdx.x; j < checks; j += 256)
            if (ei32[2 * j + 1] != 0) nz = 1;
        #pragma unroll
        for (int o = 16; o >= 1; o >>= 1)
            nz |= __shfl_xor_sync(0xffffffffu, nz, o);
        __shared__ int s_nz[8];
        if ((threadIdx.x & 31) == 0) s_nz[threadIdx.x >> 5] = nz;
        __syncthreads();
        if (threadIdx.x == 0) {
            int a = 0;
            for (int w = 0; w < 8; w++) a |= s_nz[w];
            g_is64 = (a == 0) ? 1 : 0;
        }
    }
}

__device__ __forceinline__ int edge_src(const void* ei, int E, int e) {
    if (g_is64) return (int)((const long long*)ei)[e];
    return ((const int*)ei)[e];
}
__device__ __forceinline__ int edge_dst(const void* ei, int E, int e) {
    if (g_is64) return (int)((const long long*)ei)[E + e];
    return ((const int*)ei)[E + e];
}

// ---------------- Kernel 1: h = x @ W (no epilogue logits) --------------
__global__ __launch_bounds__(256, 2)
void gemm_kernel(const float* __restrict__ x, const float* __restrict__ W, int n)
{
    extern __shared__ float smem[];
    float* ws = smem;              // [128][128] = 64KB
    float* xs = smem + 128 * 128;  // [64][128]  = 32KB

    int rowbase = blockIdx.x * 64;

    const float4* W4 = (const float4*)W;
    float4* ws4 = (float4*)ws;
    #pragma unroll
    for (int t = threadIdx.x; t < 4096; t += 256) ws4[t] = W4[t];

    float4* xs4 = (float4*)xs;
    const float4* x4in = (const float4*)x;
    #pragma unroll
    for (int t = threadIdx.x; t < 2048; t += 256) {
        int r = t >> 5, k4 = t & 31;
        int grow = rowbase + r;
        float4 v = make_float4(0.f, 0.f, 0.f, 0.f);
        if (grow < n) v = x4in[grow * 32 + k4];
        xs4[r * 32 + k4] = v;
    }
    __syncthreads();

    int rg = threadIdx.x >> 5;
    int cg = threadIdx.x & 31;

    unsigned long long acc0[8], acc1[8];
    #pragma unroll
    for (int i = 0; i < 8; i++) { acc0[i] = 0ull; acc1[i] = 0ull; }

    const float* xrow = xs + rg * 8 * 128;
    const ulonglong2* ws2 = (const ulonglong2*)ws;

    #pragma unroll 4
    for (int k4 = 0; k4 < 32; k4++) {
        ulonglong2 wv0 = ws2[(k4 * 4 + 0) * 32 + cg];
        ulonglong2 wv1 = ws2[(k4 * 4 + 1) * 32 + cg];
        ulonglong2 wv2 = ws2[(k4 * 4 + 2) * 32 + cg];
        ulonglong2 wv3 = ws2[(k4 * 4 + 3) * 32 + cg];
        #pragma unroll
        for (int i = 0; i < 8; i++) {
            float4 xv = *(const float4*)(xrow + i * 128 + k4 * 4);
            unsigned long long p0 = pk2(xv.x, xv.x);
            unsigned long long p1 = pk2(xv.y, xv.y);
            unsigned long long p2 = pk2(xv.z, xv.z);
            unsigned long long p3 = pk2(xv.w, xv.w);
            acc0[i] = fma2(p0, wv0.x, acc0[i]); acc1[i] = fma2(p0, wv0.y, acc1[i]);
            acc0[i] = fma2(p1, wv1.x, acc0[i]); acc1[i] = fma2(p1, wv1.y, acc1[i]);
            acc0[i] = fma2(p2, wv2.x, acc0[i]); acc1[i] = fma2(p2, wv2.y, acc1[i]);
            acc0[i] = fma2(p3, wv3.x, acc0[i]); acc1[i] = fma2(p3, wv3.y, acc1[i]);
        }
    }

    float4* h4 = (float4*)g_h;
    #pragma unroll
    for (int i = 0; i < 8; i++) {
        int grow = rowbase + rg * 8 + i;
        if (grow < n) {
            float2 a = upk2(acc0[i]);
            float2 b = upk2(acc1[i]);
            h4[grow * 32 + cg] = make_float4(a.x, a.y, b.x, b.y);
        }
    }
}

// ---------------- Kernel B1: fold wa = W @ att (128 x 8) ----------------
__global__ __launch_bounds__(128)
void wa_kernel(const float* __restrict__ W,
               const float* __restrict__ att_src, const float* __restrict__ att_dst)
{
    int k = threadIdx.x;   // one thread per k-row
    float s[4] = {0.f, 0.f, 0.f, 0.f}, d[4] = {0.f, 0.f, 0.f, 0.f};
    const float* wr = W + k * 128;
    #pragma unroll 4
    for (int c = 0; c < 128; c++) {
        float w = wr[c];
        int hd = c >> 5;
        s[hd] = fmaf(w, att_src[c], s[hd]);
        d[hd] = fmaf(w, att_dst[c], d[hd]);
    }
    float4* wa4 = (float4*)g_wa;
    wa4[k * 2 + 0] = make_float4(s[0], s[1], s[2], s[3]);
    wa4[k * 2 + 1] = make_float4(d[0], d[1], d[2], d[3]);
}

// ---------------- Kernel B2: asrc/adst = x @ wa (GEMV) ------------------
__global__ __launch_bounds__(256)
void logits_kernel(const float* __restrict__ x, int n)
{
    int node = blockIdx.x * 8 + (threadIdx.x >> 5);
    if (node >= n) return;
    int lane = threadIdx.x & 31;

    float4 xv = ((const float4*)x)[node * 32 + lane];
    const float4* wa4 = (const float4*)g_wa;

    float4 vs = make_float4(0.f, 0.f, 0.f, 0.f);
    float4 vd = make_float4(0.f, 0.f, 0.f, 0.f);
    #pragma unroll
    for (int j = 0; j < 4; j++) {
        int k = lane * 4 + j;
        float xk = (j == 0) ? xv.x : (j == 1) ? xv.y : (j == 2) ? xv.z : xv.w;
        float4 ws_ = wa4[k * 2 + 0];
        float4 wd_ = wa4[k * 2 + 1];
        vs.x = fmaf(xk, ws_.x, vs.x); vs.y = fmaf(xk, ws_.y, vs.y);
        vs.z = fmaf(xk, ws_.z, vs.z); vs.w = fmaf(xk, ws_.w, vs.w);
        vd.x = fmaf(xk, wd_.x, vd.x); vd.y = fmaf(xk, wd_.y, vd.y);
        vd.z = fmaf(xk, wd_.z, vd.z); vd.w = fmaf(xk, wd_.w, vd.w);
    }
    #pragma unroll
    for (int o = 16; o >= 1; o >>= 1) {
        vs.x += __shfl_xor_sync(0xffffffffu, vs.x, o);
        vs.y += __shfl_xor_sync(0xffffffffu, vs.y, o);
        vs.z += __shfl_xor_sync(0xffffffffu, vs.z, o);
        vs.w += __shfl_xor_sync(0xffffffffu, vs.w, o);
        vd.x += __shfl_xor_sync(0xffffffffu, vd.x, o);
        vd.y += __shfl_xor_sync(0xffffffffu, vd.y, o);
        vd.z += __shfl_xor_sync(0xffffffffu, vd.z, o);
        vd.w += __shfl_xor_sync(0xffffffffu, vd.w, o);
    }
    if (lane == 0) {
        ((float4*)g_asrc)[node] = vs;
        ((float4*)g_adst)[node] = vd;
    }
}

// ---------------- CSR build kernels (proven) ----------------------------
__global__ void hist_kernel(const void* __restrict__ ei, int E)
{
    int e = blockIdx.x * 256 + threadIdx.x;
    if (e < E) atomicAdd(&g_deg[edge_dst(ei, E, e)], 1);
}

__global__ __launch_bounds__(256)
void scan_local_kernel(int n)
{
    int i = blockIdx.x * 256 + threadIdx.x;
    int lane = threadIdx.x & 31;
    int wid  = threadIdx.x >> 5;
    int v = (i < n) ? g_deg[i] : 0;
    int inc = v;
    #pragma unroll
    for (int o = 1; o < 32; o <<= 1) {
        int t = __shfl_up_sync(0xffffffffu, inc, o);
        if (lane >= o) inc += t;
    }
    __shared__ int wsum[8];
    if (lane == 31) wsum[wid] = inc;
    __syncthreads();
    if (wid == 0) {
        int ws = (lane < 8) ? wsum[lane] : 0;
        #pragma unroll
        for (int o = 1; o < 8; o <<= 1) {
            int t = __shfl_up_sync(0xffffffffu, ws, o);
            if (lane >= o) ws += t;
        }
        if (lane < 8) wsum[lane] = ws;
    }
    __syncthreads();
    int warpbase = (wid == 0) ? 0 : wsum[wid - 1];
    int excl = warpbase + inc - v;
    if (i < n) g_rowoff[i] = excl;
    if (threadIdx.x == 255) g_bsum[blockIdx.x] = warpbase + inc;
}

__global__ __launch_bounds__(256)
void scan_fixup_kernel(int n, int nb)
{
    __shared__ int s_base;
    if (threadIdx.x < 32) {
        int b = 0;
        for (int j = threadIdx.x; j < blockIdx.x; j += 32) b += g_bsum[j];
        #pragma unroll
        for (int o = 16; o >= 1; o >>= 1)
            b += __shfl_xor_sync(0xffffffffu, b, o);
        if (threadIdx.x == 0) s_base = b;
    }
    __syncthreads();
    int i = blockIdx.x * 256 + threadIdx.x;
    if (i < n) {
        int r = g_rowoff[i] + s_base;
        g_rowoff[i] = r;
        g_cursor[i] = r;
    }
}

__global__ void scatter_kernel(const void* __restrict__ ei, int E)
{
    int e = blockIdx.x * 256 + threadIdx.x;
    if (e < E) {
        int s = edge_src(ei, E, e);
        int d = edge_dst(ei, E, e);
        int pos = atomicAdd(&g_cursor[d], 1);
        g_srclist[pos] = s;
    }
}

// ---------------- Kernel B3: per-edge softmax weights -------------------
// One warp per node. Lane-parallel over edges, all 4 heads as float4.
__global__ __launch_bounds__(256)
void edge_att_kernel(int n)
{
    int node = blockIdx.x * 8 + (threadIdx.x >> 5);
    if (node >= n) return;
    int lane = threadIdx.x & 31;

    int beg = g_rowoff[node];
    int cnt = g_deg[node];

    float4 adst4  = ((const float4*)g_adst)[node];
    float4 aself4 = ((const float4*)g_asrc)[node];
    const float4* asrc4p = (const float4*)g_asrc;

    // Pass 1: per-head max of asrc over {self} U neighbors
    float4 m4 = aself4;
    for (int base = 0; base < cnt; base += 32) {
        int k = base + lane;
        float4 a4 = (k < cnt) ? asrc4p[g_srclist[beg + k]]
                              : make_float4(-1e30f, -1e30f, -1e30f, -1e30f);
        m4.x = fmaxf(m4.x, a4.x); m4.y = fmaxf(m4.y, a4.y);
        m4.z = fmaxf(m4.z, a4.z); m4.w = fmaxf(m4.w, a4.w);
    }
    #pragma unroll
    for (int o = 16; o >= 1; o >>= 1) {
        m4.x = fmaxf(m4.x, __shfl_xor_sync(0xffffffffu, m4.x, o));
        m4.y = fmaxf(m4.y, __shfl_xor_sync(0xffffffffu, m4.y, o));
        m4.z = fmaxf(m4.z, __shfl_xor_sync(0xffffffffu, m4.z, o));
        m4.w = fmaxf(m4.w, __shfl_xor_sync(0xffffffffu, m4.w, o));
    }
    float4 M4 = lrelu4(make_float4(m4.x + adst4.x, m4.y + adst4.y,
                                   m4.z + adst4.z, m4.w + adst4.w));

    // self-loop
    float4 es4 = lrelu4(make_float4(aself4.x + adst4.x, aself4.y + adst4.y,
                                    aself4.z + adst4.z, aself4.w + adst4.w));
    float4 ps4 = make_float4(__expf(es4.x - M4.x), __expf(es4.y - M4.y),
                             __expf(es4.z - M4.z), __expf(es4.w - M4.w));
    float4 den4 = (lane == 0) ? ps4 : make_float4(0.f, 0.f, 0.f, 0.f);

    // Pass 2: exp + store alpha + accumulate denominator
    float4* alpha4 = (float4*)g_alpha;
    for (int base = 0; base < cnt; base += 32) {
        int k = base + lane;
        if (k < cnt) {
            float4 a4 = asrc4p[g_srclist[beg + k]];
            float4 e4 = lrelu4(make_float4(a4.x + adst4.x, a4.y + adst4.y,
                                           a4.z + adst4.z, a4.w + adst4.w));
            float4 p4 = make_float4(__expf(e4.x - M4.x), __expf(e4.y - M4.y),
                                    __expf(e4.z - M4.z), __expf(e4.w - M4.w));
            alpha4[beg + k] = p4;
            den4.x += p4.x; den4.y += p4.y; den4.z += p4.z; den4.w += p4.w;
        }
    }
    #pragma unroll
    for (int o = 16; o >= 1; o >>= 1) {
        den4.x += __shfl_xor_sync(0xffffffffu, den4.x, o);
        den4.y += __shfl_xor_sync(0xffffffffu, den4.y, o);
        den4.z += __shfl_xor_sync(0xffffffffu, den4.z, o);
        den4.w += __shfl_xor_sync(0xffffffffu, den4.w, o);
    }
    if (lane == 0) {
        ((float4*)g_pself)[node] = ps4;
        ((float4*)g_den)[node]   = den4;
    }
}

// ---------------- Kernel 5: gather-aggregate + GELU + LN + residual -----
// Per edge: sequential srclist/alpha loads + one h gather + FMA. All
// attention math precomputed in stream B.
__global__ __launch_bounds__(256)
void agg_ln_kernel(const float* __restrict__ x,
                   const float* __restrict__ bias,
                   const float* __restrict__ gamma,
                   const float* __restrict__ beta,
                   float* __restrict__ out, int n)
{
    int node = blockIdx.x * 8 + (threadIdx.x >> 5);
    if (node >= n) return;
    int lane = threadIdx.x & 31;
    int hd8 = lane >> 3;

    int beg = g_rowoff[node];
    int cnt = g_deg[node];

    float pself = g_pself[node * HH + hd8];
    float den   = g_den[node * HH + hd8];
    float inv = 1.0f / den;

    const float4* h4 = (const float4*)g_h;
    float4 hv = h4[node * 32 + lane];
    float4 accA = make_float4(pself * hv.x, pself * hv.y,
                              pself * hv.z, pself * hv.w);
    float4 accB = make_float4(0.f, 0.f, 0.f, 0.f);

    int k = 0;
    for (; k + 2 <= cnt; k += 2) {
        int sa = g_srclist[beg + k];
        int sb = g_srclist[beg + k + 1];
        float pa = g_alpha[(beg + k) * HH + hd8];
        float pb = g_alpha[(beg + k + 1) * HH + hd8];
        float4 ha = h4[sa * 32 + lane];
        float4 hb = h4[sb * 32 + lane];
        accA.x = fmaf(pa, ha.x, accA.x); accA.y = fmaf(pa, ha.y, accA.y);
        accA.z = fmaf(pa, ha.z, accA.z); accA.w = fmaf(pa, ha.w, accA.w);
        accB.x = fmaf(pb, hb.x, accB.x); accB.y = fmaf(pb, hb.y, accB.y);
        accB.z = fmaf(pb, hb.z, accB.z); accB.w = fmaf(pb, hb.w, accB.w);
    }
    if (k < cnt) {
        int sa = g_srclist[beg + k];
        float pa = g_alpha[(beg + k) * HH + hd8];
        float4 ha = h4[sa * 32 + lane];
        accA.x = fmaf(pa, ha.x, accA.x); accA.y = fmaf(pa, ha.y, accA.y);
        accA.z = fmaf(pa, ha.z, accA.z); accA.w = fmaf(pa, ha.w, accA.w);
    }

    float4 bi = ((const float4*)bias)[lane];
    float4 o = make_float4(fmaf(accA.x + accB.x, inv, bi.x),
                           fmaf(accA.y + accB.y, inv, bi.y),
                           fmaf(accA.z + accB.z, inv, bi.z),
                           fmaf(accA.w + accB.w, inv, bi.w));

    const float RS2 = 0.70710678118654752f;
    float4 f;
    f.x = 0.5f * o.x * (1.0f + erff(o.x * RS2));
    f.y = 0.5f * o.y * (1.0f + erff(o.y * RS2));
    f.z = 0.5f * o.z * (1.0f + erff(o.z * RS2));
    f.w = 0.5f * o.w * (1.0f + erff(o.w * RS2));

    float s1 = f.x + f.y + f.z + f.w;
    float s2 = f.x * f.x + f.y * f.y + f.z * f.z + f.w * f.w;
    #pragma unroll
    for (int off = 16; off >= 1; off >>= 1) {
        s1 += __shfl_xor_sync(0xffffffffu, s1, off);
        s2 += __shfl_xor_sync(0xffffffffu, s2, off);
    }
    float mu  = s1 * (1.0f / 128.0f);
    float var = s2 * (1.0f / 128.0f) - mu * mu;
    float r = rsqrtf(var + LN_EPS);

    float4 gm = ((const float4*)gamma)[lane];
    float4 bt = ((const float4*)beta)[lane];
    float4 xv = ((const float4*)x)[node * 32 + lane];
    float4 res;
    res.x = (f.x - mu) * r * gm.x + bt.x + xv.x;
    res.y = (f.y - mu) * r * gm.y + bt.y + xv.y;
    res.z = (f.z - mu) * r * gm.z + bt.z + xv.z;
    res.w = (f.w - mu) * r * gm.w + bt.w + xv.w;
    ((float4*)out)[node * 32 + lane] = res;
}

// ---------------- launch: gemm || (CSR + logits + edge-att), join at agg
extern "C" void kernel_launch(void* const* d_in, const int* in_sizes, int n_in,
                              void* d_out, int out_size)
{
    const float* x       = (const float*)d_in[0];
    const void*  ei      = d_in[1];
    const float* W       = (const float*)d_in[2];
    const float* att_src = (const float*)d_in[3];
    const float* att_dst = (const float*)d_in[4];
    const float* bias    = (const float*)d_in[5];
    const float* gamma   = (const float*)d_in[6];
    const float* beta    = (const float*)d_in[7];
    float*       out     = (float*)d_out;

    int n = in_sizes[0] / DD;     // 50000
    int E = in_sizes[1] / 2;      // 600000
    int nb = (n + 255) / 256;     // 196

    const int GEMM_SMEM = (128 * 128 + 64 * 128) * 4;  // 96KB
    static bool s_init = false;
    static cudaStream_t s2;
    static cudaEvent_t evFork, evJoin;
    if (!s_init) {
        cudaFuncSetAttribute(gemm_kernel,
                             cudaFuncAttributeMaxDynamicSharedMemorySize, GEMM_SMEM);
        cudaStreamCreateWithFlags(&s2, cudaStreamNonBlocking);
        cudaEventCreateWithFlags(&evFork, cudaEventDisableTiming);
        cudaEventCreateWithFlags(&evJoin, cudaEventDisableTiming);
        s_init = true;
    }

    cudaEventRecord(evFork, 0);
    cudaStreamWaitEvent(s2, evFork, 0);

    // Chain A (default stream): dense GEMM h = x @ W
    gemm_kernel<<<(n + 63) / 64, 256, GEMM_SMEM>>>(x, W, n);

    // Chain B (side stream): logits + CSR + per-edge softmax weights
    wa_kernel<<<1, 128, 0, s2>>>(W, att_src, att_dst);
    detect_zero_kernel<<<nb, 256, 0, s2>>>((const int*)ei, E, n);
    logits_kernel<<<(n + 7) / 8, 256, 0, s2>>>(x, n);
    hist_kernel<<<(E + 255) / 256, 256, 0, s2>>>(ei, E);
    scan_local_kernel<<<nb, 256, 0, s2>>>(n);
    scan_fixup_kernel<<<nb, 256, 0, s2>>>(n, nb);
    scatter_kernel<<<(E + 255) / 256, 256, 0, s2>>>(ei, E);
    edge_att_kernel<<<(n + 7) / 8, 256, 0, s2>>>(n);

    // Join: agg depends on both chains.
    cudaEventRecord(evJoin, s2);
    cudaStreamWaitEvent(0, evJoin, 0);

    agg_ln_kernel<<<(n + 7) / 8, 256>>>(x, bias, gamma, beta, out, n);
}

// round 12
// speedup vs baseline: 1.6075x; 1.6075x over previous
#include <cuda_runtime.h>
#include <cuda_bf16.h>
#include <math.h>

#define NN_MAX 50000
#define EE_MAX 600000
#define DD 128
#define HH 4
#define CC 32
#define NEG_SLOPE 0.2f
#define LN_EPS 1e-5f
#define NB_MAX 256

// ---------------- device scratch ----------------
static __device__ float g_h[NN_MAX * DD];
static __device__ float g_asrc[NN_MAX * HH];
static __device__ float g_adst[NN_MAX * HH];
static __device__ float g_alpha[EE_MAX * HH];   // per-edge unnormalized weight
static __device__ float g_pself[NN_MAX * HH];   // self-loop weight
static __device__ float g_den[NN_MAX * HH];     // softmax denominator
static __device__ int   g_deg[NN_MAX];
static __device__ int   g_rowoff[NN_MAX];
static __device__ int   g_cursor[NN_MAX];
static __device__ int   g_srclist[EE_MAX];
static __device__ int   g_bsum[NB_MAX];
static __device__ int   g_is64;

// ---------------- f32x2 helpers ----------------
__device__ __forceinline__ unsigned long long pk2(float lo, float hi) {
    unsigned long long r;
    asm("mov.b64 %0, {%1, %2};" : "=l"(r) : "f"(lo), "f"(hi));
    return r;
}
__device__ __forceinline__ unsigned long long fma2(unsigned long long a,
                                                   unsigned long long b,
                                                   unsigned long long c) {
    unsigned long long d;
    asm("fma.rn.f32x2 %0, %1, %2, %3;" : "=l"(d) : "l"(a), "l"(b), "l"(c));
    return d;
}
__device__ __forceinline__ float2 upk2(unsigned long long v) {
    float lo, hi;
    asm("mov.b64 {%0, %1}, %2;" : "=f"(lo), "=f"(hi) : "l"(v));
    return make_float2(lo, hi);
}
__device__ __forceinline__ float lrelu(float v) {
    return (v > 0.f) ? v : v * NEG_SLOPE;
}
__device__ __forceinline__ float4 lrelu4(float4 v) {
    return make_float4(lrelu(v.x), lrelu(v.y), lrelu(v.z), lrelu(v.w));
}

// ---------------- Kernel 0: zero degrees + detect dtype ----------------
__global__ void detect_zero_kernel(const int* __restrict__ ei32, int E, int n)
{
    int i = blockIdx.x * 256 + threadIdx.x;
    if (i < n) g_deg[i] = 0;
    if (blockIdx.x == 0) {
        int checks = 2 * E; if (checks > 4096) checks = 4096;
        int nz = 0;
        for (int j = threadIdx.x; j < checks; j += 256)
            if (ei32[2 * j + 1] != 0) nz = 1;
        #pragma unroll
        for (int o = 16; o >= 1; o >>= 1)
            nz |= __shfl_xor_sync(0xffffffffu, nz, o);
        __shared__ int s_nz[8];
        if ((threadIdx.x & 31) == 0) s_nz[threadIdx.x >> 5] = nz;
        __syncthreads();
        if (threadIdx.x == 0) {
            int a = 0;
            for (int w = 0; w < 8; w++) a |= s_nz[w];
            g_is64 = (a == 0) ? 1 : 0;
        }
    }
}

__device__ __forceinline__ int edge_src(const void* ei, int E, int e) {
    if (g_is64) return (int)((const long long*)ei)[e];
    return ((const int*)ei)[e];
}
__device__ __forceinline__ int edge_dst(const void* ei, int E, int e) {
    if (g_is64) return (int)((const long long*)ei)[E + e];
    return ((const int*)ei)[E + e];
}

// ---------------- Kernel 1: h = x @ W + fused attention logits ----------
// (R9 proven version — epilogue computes asrc/adst nearly for free)
__global__ __launch_bounds__(256, 2)
void gemm_kernel(const float* __restrict__ x, const float* __restrict__ W,
                 const float* __restrict__ att_src, const float* __restrict__ att_dst,
                 int n)
{
    extern __shared__ float smem[];
    float* ws = smem;              // [128][128] = 64KB
    float* xs = smem + 128 * 128;  // [64][128]  = 32KB

    int rowbase = blockIdx.x * 64;

    const float4* W4 = (const float4*)W;
    float4* ws4 = (float4*)ws;
    #pragma unroll
    for (int t = threadIdx.x; t < 4096; t += 256) ws4[t] = W4[t];

    float4* xs4 = (float4*)xs;
    const float4* x4in = (const float4*)x;
    #pragma unroll
    for (int t = threadIdx.x; t < 2048; t += 256) {
        int r = t >> 5, k4 = t & 31;
        int grow = rowbase + r;
        float4 v = make_float4(0.f, 0.f, 0.f, 0.f);
        if (grow < n) v = x4in[grow * 32 + k4];
        xs4[r * 32 + k4] = v;
    }
    __syncthreads();

    int rg = threadIdx.x >> 5;
    int cg = threadIdx.x & 31;

    unsigned long long acc0[8], acc1[8];
    #pragma unroll
    for (int i = 0; i < 8; i++) { acc0[i] = 0ull; acc1[i] = 0ull; }

    const float* xrow = xs + rg * 8 * 128;
    const ulonglong2* ws2 = (const ulonglong2*)ws;

    #pragma unroll 4
    for (int k4 = 0; k4 < 32; k4++) {
        ulonglong2 wv0 = ws2[(k4 * 4 + 0) * 32 + cg];
        ulonglong2 wv1 = ws2[(k4 * 4 + 1) * 32 + cg];
        ulonglong2 wv2 = ws2[(k4 * 4 + 2) * 32 + cg];
        ulonglong2 wv3 = ws2[(k4 * 4 + 3) * 32 + cg];
        #pragma unroll
        for (int i = 0; i < 8; i++) {
            float4 xv = *(const float4*)(xrow + i * 128 + k4 * 4);
            unsigned long long p0 = pk2(xv.x, xv.x);
            unsigned long long p1 = pk2(xv.y, xv.y);
            unsigned long long p2 = pk2(xv.z, xv.z);
            unsigned long long p3 = pk2(xv.w, xv.w);
            acc0[i] = fma2(p0, wv0.x, acc0[i]); acc1[i] = fma2(p0, wv0.y, acc1[i]);
            acc0[i] = fma2(p1, wv1.x, acc0[i]); acc1[i] = fma2(p1, wv1.y, acc1[i]);
            acc0[i] = fma2(p2, wv2.x, acc0[i]); acc1[i] = fma2(p2, wv2.y, acc1[i]);
            acc0[i] = fma2(p3, wv3.x, acc0[i]); acc1[i] = fma2(p3, wv3.y, acc1[i]);
        }
    }

    float4 as4 = ((const float4*)att_src)[cg];
    float4 ad4 = ((const float4*)att_dst)[cg];
    float4* h4 = (float4*)g_h;
    int head = cg >> 3;

    #pragma unroll
    for (int i = 0; i < 8; i++) {
        float2 a = upk2(acc0[i]);
        float2 b = upk2(acc1[i]);
        float4 hv = make_float4(a.x, a.y, b.x, b.y);
        float ps = hv.x * as4.x + hv.y * as4.y + hv.z * as4.z + hv.w * as4.w;
        float pd = hv.x * ad4.x + hv.y * ad4.y + hv.z * ad4.z + hv.w * ad4.w;
        #pragma unroll
        for (int o = 4; o >= 1; o >>= 1) {
            ps += __shfl_xor_sync(0xffffffffu, ps, o);
            pd += __shfl_xor_sync(0xffffffffu, pd, o);
        }
        int grow = rowbase + rg * 8 + i;
        if (grow < n) {
            h4[grow * 32 + cg] = hv;
            if ((cg & 7) == 0) {
                g_asrc[grow * HH + head] = ps;
                g_adst[grow * HH + head] = pd;
            }
        }
    }
}

// ---------------- CSR build kernels (proven) ----------------------------
__global__ void hist_kernel(const void* __restrict__ ei, int E)
{
    int e = blockIdx.x * 256 + threadIdx.x;
    if (e < E) atomicAdd(&g_deg[edge_dst(ei, E, e)], 1);
}

__global__ __launch_bounds__(256)
void scan_local_kernel(int n)
{
    int i = blockIdx.x * 256 + threadIdx.x;
    int lane = threadIdx.x & 31;
    int wid  = threadIdx.x >> 5;
    int v = (i < n) ? g_deg[i] : 0;
    int inc = v;
    #pragma unroll
    for (int o = 1; o < 32; o <<= 1) {
        int t = __shfl_up_sync(0xffffffffu, inc, o);
        if (lane >= o) inc += t;
    }
    __shared__ int wsum[8];
    if (lane == 31) wsum[wid] = inc;
    __syncthreads();
    if (wid == 0) {
        int ws = (lane < 8) ? wsum[lane] : 0;
        #pragma unroll
        for (int o = 1; o < 8; o <<= 1) {
            int t = __shfl_up_sync(0xffffffffu, ws, o);
            if (lane >= o) ws += t;
        }
        if (lane < 8) wsum[lane] = ws;
    }
    __syncthreads();
    int warpbase = (wid == 0) ? 0 : wsum[wid - 1];
    int excl = warpbase + inc - v;
    if (i < n) g_rowoff[i] = excl;
    if (threadIdx.x == 255) g_bsum[blockIdx.x] = warpbase + inc;
}

__global__ __launch_bounds__(256)
void scan_fixup_kernel(int n, int nb)
{
    __shared__ int s_base;
    if (threadIdx.x < 32) {
        int b = 0;
        for (int j = threadIdx.x; j < blockIdx.x; j += 32) b += g_bsum[j];
        #pragma unroll
        for (int o = 16; o >= 1; o >>= 1)
            b += __shfl_xor_sync(0xffffffffu, b, o);
        if (threadIdx.x == 0) s_base = b;
    }
    __syncthreads();
    int i = blockIdx.x * 256 + threadIdx.x;
    if (i < n) {
        int r = g_rowoff[i] + s_base;
        g_rowoff[i] = r;
        g_cursor[i] = r;
    }
}

__global__ void scatter_kernel(const void* __restrict__ ei, int E)
{
    int e = blockIdx.x * 256 + threadIdx.x;
    if (e < E) {
        int s = edge_src(ei, E, e);
        int d = edge_dst(ei, E, e);
        int pos = atomicAdd(&g_cursor[d], 1);
        g_srclist[pos] = s;
    }
}

// ---------------- Kernel B3: per-edge softmax weights -------------------
// (R10 proven) One warp per node, lane-parallel over edges, 4 heads/float4.
__global__ __launch_bounds__(256)
void edge_att_kernel(int n)
{
    int node = blockIdx.x * 8 + (threadIdx.x >> 5);
    if (node >= n) return;
    int lane = threadIdx.x & 31;

    int beg = g_rowoff[node];
    int cnt = g_deg[node];

    float4 adst4  = ((const float4*)g_adst)[node];
    float4 aself4 = ((const float4*)g_asrc)[node];
    const float4* asrc4p = (const float4*)g_asrc;

    // Pass 1: per-head max of asrc over {self} U neighbors
    float4 m4 = aself4;
    for (int base = 0; base < cnt; base += 32) {
        int k = base + lane;
        float4 a4 = (k < cnt) ? asrc4p[g_srclist[beg + k]]
                              : make_float4(-1e30f, -1e30f, -1e30f, -1e30f);
        m4.x = fmaxf(m4.x, a4.x); m4.y = fmaxf(m4.y, a4.y);
        m4.z = fmaxf(m4.z, a4.z); m4.w = fmaxf(m4.w, a4.w);
    }
    #pragma unroll
    for (int o = 16; o >= 1; o >>= 1) {
        m4.x = fmaxf(m4.x, __shfl_xor_sync(0xffffffffu, m4.x, o));
        m4.y = fmaxf(m4.y, __shfl_xor_sync(0xffffffffu, m4.y, o));
        m4.z = fmaxf(m4.z, __shfl_xor_sync(0xffffffffu, m4.z, o));
        m4.w = fmaxf(m4.w, __shfl_xor_sync(0xffffffffu, m4.w, o));
    }
    float4 M4 = lrelu4(make_float4(m4.x + adst4.x, m4.y + adst4.y,
                                   m4.z + adst4.z, m4.w + adst4.w));

    // self-loop
    float4 es4 = lrelu4(make_float4(aself4.x + adst4.x, aself4.y + adst4.y,
                                    aself4.z + adst4.z, aself4.w + adst4.w));
    float4 ps4 = make_float4(__expf(es4.x - M4.x), __expf(es4.y - M4.y),
                             __expf(es4.z - M4.z), __expf(es4.w - M4.w));
    float4 den4 = (lane == 0) ? ps4 : make_float4(0.f, 0.f, 0.f, 0.f);

    // Pass 2: exp + store alpha + accumulate denominator
    float4* alpha4 = (float4*)g_alpha;
    for (int base = 0; base < cnt; base += 32) {
        int k = base + lane;
        if (k < cnt) {
            float4 a4 = asrc4p[g_srclist[beg + k]];
            float4 e4 = lrelu4(make_float4(a4.x + adst4.x, a4.y + adst4.y,
                                           a4.z + adst4.z, a4.w + adst4.w));
            float4 p4 = make_float4(__expf(e4.x - M4.x), __expf(e4.y - M4.y),
                                    __expf(e4.z - M4.z), __expf(e4.w - M4.w));
            alpha4[beg + k] = p4;
            den4.x += p4.x; den4.y += p4.y; den4.z += p4.z; den4.w += p4.w;
        }
    }
    #pragma unroll
    for (int o = 16; o >= 1; o >>= 1) {
        den4.x += __shfl_xor_sync(0xffffffffu, den4.x, o);
        den4.y += __shfl_xor_sync(0xffffffffu, den4.y, o);
        den4.z += __shfl_xor_sync(0xffffffffu, den4.z, o);
        den4.w += __shfl_xor_sync(0xffffffffu, den4.w, o);
    }
    if (lane == 0) {
        ((float4*)g_pself)[node] = ps4;
        ((float4*)g_den)[node]   = den4;
    }
}

// ---------------- Kernel 5: gather-aggregate + GELU + LN + residual -----
// (R10 proven lightweight version)
__global__ __launch_bounds__(256)
void agg_ln_kernel(const float* __restrict__ x,
                   const float* __restrict__ bias,
                   const float* __restrict__ gamma,
                   const float* __restrict__ beta,
                   float* __restrict__ out, int n)
{
    int node = blockIdx.x * 8 + (threadIdx.x >> 5);
    if (node >= n) return;
    int lane = threadIdx.x & 31;
    int hd8 = lane >> 3;

    int beg = g_rowoff[node];
    int cnt = g_deg[node];

    float pself = g_pself[node * HH + hd8];
    float den   = g_den[node * HH + hd8];
    float inv = 1.0f / den;

    const float4* h4 = (const float4*)g_h;
    float4 hv = h4[node * 32 + lane];
    float4 accA = make_float4(pself * hv.x, pself * hv.y,
                              pself * hv.z, pself * hv.w);
    float4 accB = make_float4(0.f, 0.f, 0.f, 0.f);

    int k = 0;
    for (; k + 2 <= cnt; k += 2) {
        int sa = g_srclist[beg + k];
        int sb = g_srclist[beg + k + 1];
        float pa = g_alpha[(beg + k) * HH + hd8];
        float pb = g_alpha[(beg + k + 1) * HH + hd8];
        float4 ha = h4[sa * 32 + lane];
        float4 hb = h4[sb * 32 + lane];
        accA.x = fmaf(pa, ha.x, accA.x); accA.y = fmaf(pa, ha.y, accA.y);
        accA.z = fmaf(pa, ha.z, accA.z); accA.w = fmaf(pa, ha.w, accA.w);
        accB.x = fmaf(pb, hb.x, accB.x); accB.y = fmaf(pb, hb.y, accB.y);
        accB.z = fmaf(pb, hb.z, accB.z); accB.w = fmaf(pb, hb.w, accB.w);
    }
    if (k < cnt) {
        int sa = g_srclist[beg + k];
        float pa = g_alpha[(beg + k) * HH + hd8];
        float4 ha = h4[sa * 32 + lane];
        accA.x = fmaf(pa, ha.x, accA.x); accA.y = fmaf(pa, ha.y, accA.y);
        accA.z = fmaf(pa, ha.z, accA.z); accA.w = fmaf(pa, ha.w, accA.w);
    }

    float4 bi = ((const float4*)bias)[lane];
    float4 o = make_float4(fmaf(accA.x + accB.x, inv, bi.x),
                           fmaf(accA.y + accB.y, inv, bi.y),
                           fmaf(accA.z + accB.z, inv, bi.z),
                           fmaf(accA.w + accB.w, inv, bi.w));

    const float RS2 = 0.70710678118654752f;
    float4 f;
    f.x = 0.5f * o.x * (1.0f + erff(o.x * RS2));
    f.y = 0.5f * o.y * (1.0f + erff(o.y * RS2));
    f.z = 0.5f * o.z * (1.0f + erff(o.z * RS2));
    f.w = 0.5f * o.w * (1.0f + erff(o.w * RS2));

    float s1 = f.x + f.y + f.z + f.w;
    float s2 = f.x * f.x + f.y * f.y + f.z * f.z + f.w * f.w;
    #pragma unroll
    for (int off = 16; off >= 1; off >>= 1) {
        s1 += __shfl_xor_sync(0xffffffffu, s1, off);
        s2 += __shfl_xor_sync(0xffffffffu, s2, off);
    }
    float mu  = s1 * (1.0f / 128.0f);
    float var = s2 * (1.0f / 128.0f) - mu * mu;
    float r = rsqrtf(var + LN_EPS);

    float4 gm = ((const float4*)gamma)[lane];
    float4 bt = ((const float4*)beta)[lane];
    float4 xv = ((const float4*)x)[node * 32 + lane];
    float4 res;
    res.x = (f.x - mu) * r * gm.x + bt.x + xv.x;
    res.y = (f.y - mu) * r * gm.y + bt.y + xv.y;
    res.z = (f.z - mu) * r * gm.z + bt.z + xv.z;
    res.w = (f.w - mu) * r * gm.w + bt.w + xv.w;
    ((float4*)out)[node * 32 + lane] = res;
}

// ---------------- launch: gemm(+logits) || CSR, join -> edge_att -> agg --
extern "C" void kernel_launch(void* const* d_in, const int* in_sizes, int n_in,
                              void* d_out, int out_size)
{
    const float* x       = (const float*)d_in[0];
    const void*  ei      = d_in[1];
    const float* W       = (const float*)d_in[2];
    const float* att_src = (const float*)d_in[3];
    const float* att_dst = (const float*)d_in[4];
    const float* bias    = (const float*)d_in[5];
    const float* gamma   = (const float*)d_in[6];
    const float* beta    = (const float*)d_in[7];
    float*       out     = (float*)d_out;

    int n = in_sizes[0] / DD;     // 50000
    int E = in_sizes[1] / 2;      // 600000
    int nb = (n + 255) / 256;     // 196

    const int GEMM_SMEM = (128 * 128 + 64 * 128) * 4;  // 96KB
    static bool s_init = false;
    static cudaStream_t s2;
    static cudaEvent_t evFork, evJoin;
    if (!s_init) {
        cudaFuncSetAttribute(gemm_kernel,
                             cudaFuncAttributeMaxDynamicSharedMemorySize, GEMM_SMEM);
        cudaStreamCreateWithFlags(&s2, cudaStreamNonBlocking);
        cudaEventCreateWithFlags(&evFork, cudaEventDisableTiming);
        cudaEventCreateWithFlags(&evJoin, cudaEventDisableTiming);
        s_init = true;
    }

    cudaEventRecord(evFork, 0);
    cudaStreamWaitEvent(s2, evFork, 0);

    // Chain A (default stream): GEMM + attention logits
    gemm_kernel<<<(n + 63) / 64, 256, GEMM_SMEM>>>(x, W, att_src, att_dst, n);

    // Chain B (side stream): CSR build only
    detect_zero_kernel<<<nb, 256, 0, s2>>>((const int*)ei, E, n);
    hist_kernel<<<(E + 255) / 256, 256, 0, s2>>>(ei, E);
    scan_local_kernel<<<nb, 256, 0, s2>>>(n);
    scan_fixup_kernel<<<nb, 256, 0, s2>>>(n, nb);
    scatter_kernel<<<(E + 255) / 256, 256, 0, s2>>>(ei, E);

    // Join: edge_att needs both logits (A) and CSR (B).
    cudaEventRecord(evJoin, s2);
    cudaStreamWaitEvent(0, evJoin, 0);

    edge_att_kernel<<<(n + 7) / 8, 256>>>(n);
    agg_ln_kernel<<<(n + 7) / 8, 256>>>(x, bias, gamma, beta, out, n);
}

// round 13
// speedup vs baseline: 1.7744x; 1.1038x over previous
#include <cuda_runtime.h>
#include <cuda_bf16.h>
#include <math.h>

#define NN_MAX 50000
#define EE_MAX 600000
#define DD 128
#define HH 4
#define CC 32
#define NEG_SLOPE 0.2f
#define LN_EPS 1e-5f
#define NB_MAX 256

// ---------------- device scratch ----------------
static __device__ float g_h[NN_MAX * DD];
static __device__ float g_asrc[NN_MAX * HH];
static __device__ float g_adst[NN_MAX * HH];
static __device__ int   g_deg[NN_MAX];
static __device__ int   g_rowoff[NN_MAX];
static __device__ int   g_cursor[NN_MAX];
static __device__ int   g_srclist[EE_MAX];
static __device__ int   g_bsum[NB_MAX];
static __device__ int   g_is64;

// ---------------- f32x2 helpers ----------------
__device__ __forceinline__ unsigned long long pk2(float lo, float hi) {
    unsigned long long r;
    asm("mov.b64 %0, {%1, %2};" : "=l"(r) : "f"(lo), "f"(hi));
    return r;
}
__device__ __forceinline__ unsigned long long fma2(unsigned long long a,
                                                   unsigned long long b,
                                                   unsigned long long c) {
    unsigned long long d;
    asm("fma.rn.f32x2 %0, %1, %2, %3;" : "=l"(d) : "l"(a), "l"(b), "l"(c));
    return d;
}
__device__ __forceinline__ float2 upk2(unsigned long long v) {
    float lo, hi;
    asm("mov.b64 {%0, %1}, %2;" : "=f"(lo), "=f"(hi) : "l"(v));
    return make_float2(lo, hi);
}
__device__ __forceinline__ float lrelu(float v) {
    return (v > 0.f) ? v : v * NEG_SLOPE;
}

// ---------------- Kernel 0: zero degrees + detect dtype ----------------
__global__ void detect_zero_kernel(const int* __restrict__ ei32, int E, int n)
{
    int i = blockIdx.x * 256 + threadIdx.x;
    if (i < n) g_deg[i] = 0;
    if (blockIdx.x == 0) {
        int checks = 2 * E; if (checks > 4096) checks = 4096;
        int nz = 0;
        for (int j = threadIdx.x; j < checks; j += 256)
            if (ei32[2 * j + 1] != 0) nz = 1;
        #pragma unroll
        for (int o = 16; o >= 1; o >>= 1)
            nz |= __shfl_xor_sync(0xffffffffu, nz, o);
        __shared__ int s_nz[8];
        if ((threadIdx.x & 31) == 0) s_nz[threadIdx.x >> 5] = nz;
        __syncthreads();
        if (threadIdx.x == 0) {
            int a = 0;
            for (int w = 0; w < 8; w++) a |= s_nz[w];
            g_is64 = (a == 0) ? 1 : 0;
        }
    }
}

__device__ __forceinline__ int edge_src(const void* ei, int E, int e) {
    if (g_is64) return (int)((const long long*)ei)[e];
    return ((const int*)ei)[e];
}
__device__ __forceinline__ int edge_dst(const void* ei, int E, int e) {
    if (g_is64) return (int)((const long long*)ei)[E + e];
    return ((const int*)ei)[E + e];
}

// ---------------- Kernel 1: h = x @ W + logits (persistent tiles) -------
// R9-proven math/layout; W staged ONCE per block, loop over 64-row tiles.
__global__ __launch_bounds__(256, 2)
void gemm_kernel(const float* __restrict__ x, const float* __restrict__ W,
                 const float* __restrict__ att_src, const float* __restrict__ att_dst,
                 int n, int ntiles)
{
    extern __shared__ float smem[];
    float* ws = smem;              // [128][128] = 64KB
    float* xs = smem + 128 * 128;  // [64][128]  = 32KB

    int tid = threadIdx.x;
    int rg = tid >> 5;
    int cg = tid & 31;

    // Stage W once per block
    const float4* W4 = (const float4*)W;
    float4* ws4 = (float4*)ws;
    #pragma unroll
    for (int t = tid; t < 4096; t += 256) ws4[t] = W4[t];

    float4 as4 = ((const float4*)att_src)[cg];
    float4 ad4 = ((const float4*)att_dst)[cg];
    float4* h4 = (float4*)g_h;
    const float4* x4in = (const float4*)x;
    float4* xs4 = (float4*)xs;
    const float* xrow = xs + rg * 8 * 128;
    const ulonglong2* ws2 = (const ulonglong2*)ws;
    int head = cg >> 3;

    for (int tile = blockIdx.x; tile < ntiles; tile += gridDim.x) {
        int rowbase = tile * 64;

        __syncthreads();   // previous tile's xs readers done (1st iter: W visible after next sync)
        #pragma unroll
        for (int t = tid; t < 2048; t += 256) {
            int r = t >> 5, k4 = t & 31;
            int grow = rowbase + r;
            float4 v = make_float4(0.f, 0.f, 0.f, 0.f);
            if (grow < n) v = x4in[grow * 32 + k4];
            xs4[r * 32 + k4] = v;
        }
        __syncthreads();

        unsigned long long acc0[8], acc1[8];
        #pragma unroll
        for (int i = 0; i < 8; i++) { acc0[i] = 0ull; acc1[i] = 0ull; }

        #pragma unroll 4
        for (int k4 = 0; k4 < 32; k4++) {
            ulonglong2 wv0 = ws2[(k4 * 4 + 0) * 32 + cg];
            ulonglong2 wv1 = ws2[(k4 * 4 + 1) * 32 + cg];
            ulonglong2 wv2 = ws2[(k4 * 4 + 2) * 32 + cg];
            ulonglong2 wv3 = ws2[(k4 * 4 + 3) * 32 + cg];
            #pragma unroll
            for (int i = 0; i < 8; i++) {
                float4 xv = *(const float4*)(xrow + i * 128 + k4 * 4);
                unsigned long long p0 = pk2(xv.x, xv.x);
                unsigned long long p1 = pk2(xv.y, xv.y);
                unsigned long long p2 = pk2(xv.z, xv.z);
                unsigned long long p3 = pk2(xv.w, xv.w);
                acc0[i] = fma2(p0, wv0.x, acc0[i]); acc1[i] = fma2(p0, wv0.y, acc1[i]);
                acc0[i] = fma2(p1, wv1.x, acc0[i]); acc1[i] = fma2(p1, wv1.y, acc1[i]);
                acc0[i] = fma2(p2, wv2.x, acc0[i]); acc1[i] = fma2(p2, wv2.y, acc1[i]);
                acc0[i] = fma2(p3, wv3.x, acc0[i]); acc1[i] = fma2(p3, wv3.y, acc1[i]);
            }
        }

        #pragma unroll
        for (int i = 0; i < 8; i++) {
            float2 a = upk2(acc0[i]);
            float2 b = upk2(acc1[i]);
            float4 hv = make_float4(a.x, a.y, b.x, b.y);
            float ps = hv.x * as4.x + hv.y * as4.y + hv.z * as4.z + hv.w * as4.w;
            float pd = hv.x * ad4.x + hv.y * ad4.y + hv.z * ad4.z + hv.w * ad4.w;
            #pragma unroll
            for (int o = 4; o >= 1; o >>= 1) {
                ps += __shfl_xor_sync(0xffffffffu, ps, o);
                pd += __shfl_xor_sync(0xffffffffu, pd, o);
            }
            int grow = rowbase + rg * 8 + i;
            if (grow < n) {
                h4[grow * 32 + cg] = hv;
                if ((cg & 7) == 0) {
                    g_asrc[grow * HH + head] = ps;
                    g_adst[grow * HH + head] = pd;
                }
            }
        }
    }
}

// ---------------- CSR build kernels (proven) ----------------------------
__global__ void hist_kernel(const void* __restrict__ ei, int E)
{
    int e = blockIdx.x * 256 + threadIdx.x;
    if (e < E) atomicAdd(&g_deg[edge_dst(ei, E, e)], 1);
}

__global__ __launch_bounds__(256)
void scan_local_kernel(int n)
{
    int i = blockIdx.x * 256 + threadIdx.x;
    int lane = threadIdx.x & 31;
    int wid  = threadIdx.x >> 5;
    int v = (i < n) ? g_deg[i] : 0;
    int inc = v;
    #pragma unroll
    for (int o = 1; o < 32; o <<= 1) {
        int t = __shfl_up_sync(0xffffffffu, inc, o);
        if (lane >= o) inc += t;
    }
    __shared__ int wsum[8];
    if (lane == 31) wsum[wid] = inc;
    __syncthreads();
    if (wid == 0) {
        int ws = (lane < 8) ? wsum[lane] : 0;
        #pragma unroll
        for (int o = 1; o < 8; o <<= 1) {
            int t = __shfl_up_sync(0xffffffffu, ws, o);
            if (lane >= o) ws += t;
        }
        if (lane < 8) wsum[lane] = ws;
    }
    __syncthreads();
    int warpbase = (wid == 0) ? 0 : wsum[wid - 1];
    int excl = warpbase + inc - v;
    if (i < n) g_rowoff[i] = excl;
    if (threadIdx.x == 255) g_bsum[blockIdx.x] = warpbase + inc;
}

__global__ __launch_bounds__(256)
void scan_fixup_kernel(int n, int nb)
{
    __shared__ int s_base;
    if (threadIdx.x < 32) {
        int b = 0;
        for (int j = threadIdx.x; j < blockIdx.x; j += 32) b += g_bsum[j];
        #pragma unroll
        for (int o = 16; o >= 1; o >>= 1)
            b += __shfl_xor_sync(0xffffffffu, b, o);
        if (threadIdx.x == 0) s_base = b;
    }
    __syncthreads();
    int i = blockIdx.x * 256 + threadIdx.x;
    if (i < n) {
        int r = g_rowoff[i] + s_base;
        g_rowoff[i] = r;
        g_cursor[i] = r;
    }
}

__global__ void scatter_kernel(const void* __restrict__ ei, int E)
{
    int e = blockIdx.x * 256 + threadIdx.x;
    if (e < E) {
        int s = edge_src(ei, E, e);
        int d = edge_dst(ei, E, e);
        int pos = atomicAdd(&g_cursor[d], 1);
        g_srclist[pos] = s;
    }
}

// ---------------- Kernel 5: fused softmax-agg + GELU + LN + residual ----
// Monolithic (R3 structure) with 4 independent chains (R6 agg body).
__global__ __launch_bounds__(256)
void agg_ln_kernel(const float* __restrict__ x,
                   const float* __restrict__ bias,
                   const float* __restrict__ gamma,
                   const float* __restrict__ beta,
                   float* __restrict__ out, int n)
{
    int node = blockIdx.x * 8 + (threadIdx.x >> 5);
    if (node >= n) return;
    int lane = threadIdx.x & 31;
    int hd8 = lane >> 3;
    int hd4 = lane & 3;
    int esub = lane >> 2;

    int beg = g_rowoff[node];
    int cnt = g_deg[node];

    float aself = g_asrc[node * HH + hd4];
    float adst4 = g_adst[node * HH + hd4];

    // Phase A: per-head max of a_src over {self} U neighbors
    float mx = aself;
    for (int k0 = 0; k0 < cnt; k0 += 8) {
        int k = k0 + esub;
        float v = -1e30f;
        if (k < cnt) {
            int s = g_srclist[beg + k];
            v = g_asrc[s * HH + hd4];
        }
        mx = fmaxf(mx, v);
    }
    mx = fmaxf(mx, __shfl_xor_sync(0xffffffffu, mx, 4));
    mx = fmaxf(mx, __shfl_xor_sync(0xffffffffu, mx, 8));
    mx = fmaxf(mx, __shfl_xor_sync(0xffffffffu, mx, 16));

    float mxh    = __shfl_sync(0xffffffffu, mx, hd8);
    float adst   = __shfl_sync(0xffffffffu, adst4, hd8);
    float aselfh = __shfl_sync(0xffffffffu, aself, hd8);
    float M = lrelu(mxh + adst);

    // Phase B: weighted aggregation, 4 independent chains
    const float4* h4 = (const float4*)g_h;
    float p0 = __expf(lrelu(aselfh + adst) - M);
    float4 hv = h4[node * 32 + lane];
    float4 accA = make_float4(p0 * hv.x, p0 * hv.y, p0 * hv.z, p0 * hv.w);
    float4 accB = make_float4(0.f, 0.f, 0.f, 0.f);
    float4 accC = make_float4(0.f, 0.f, 0.f, 0.f);
    float4 accD = make_float4(0.f, 0.f, 0.f, 0.f);
    float dA = p0, dB = 0.f, dC = 0.f, dD = 0.f;

    int k = 0;
    for (; k + 4 <= cnt; k += 4) {
        int sa = g_srclist[beg + k];
        int sb = g_srclist[beg + k + 1];
        int sc = g_srclist[beg + k + 2];
        int sd = g_srclist[beg + k + 3];
        float ea = g_asrc[sa * HH + hd8];
        float eb = g_asrc[sb * HH + hd8];
        float ec = g_asrc[sc * HH + hd8];
        float ed = g_asrc[sd * HH + hd8];
        float4 ha = h4[sa * 32 + lane];
        float4 hb = h4[sb * 32 + lane];
        float4 hc = h4[sc * 32 + lane];
        float4 hd = h4[sd * 32 + lane];
        float pa = __expf(lrelu(ea + adst) - M);
        float pb = __expf(lrelu(eb + adst) - M);
        float pc = __expf(lrelu(ec + adst) - M);
        float pd = __expf(lrelu(ed + adst) - M);
        dA += pa; dB += pb; dC += pc; dD += pd;
        accA.x = fmaf(pa, ha.x, accA.x); accA.y = fmaf(pa, ha.y, accA.y);
        accA.z = fmaf(pa, ha.z, accA.z); accA.w = fmaf(pa, ha.w, accA.w);
        accB.x = fmaf(pb, hb.x, accB.x); accB.y = fmaf(pb, hb.y, accB.y);
        accB.z = fmaf(pb, hb.z, accB.z); accB.w = fmaf(pb, hb.w, accB.w);
        accC.x = fmaf(pc, hc.x, accC.x); accC.y = fmaf(pc, hc.y, accC.y);
        accC.z = fmaf(pc, hc.z, accC.z); accC.w = fmaf(pc, hc.w, accC.w);
        accD.x = fmaf(pd, hd.x, accD.x); accD.y = fmaf(pd, hd.y, accD.y);
        accD.z = fmaf(pd, hd.z, accD.z); accD.w = fmaf(pd, hd.w, accD.w);
    }
    for (; k < cnt; k++) {
        int sa = g_srclist[beg + k];
        float ea = g_asrc[sa * HH + hd8];
        float4 ha = h4[sa * 32 + lane];
        float pa = __expf(lrelu(ea + adst) - M);
        dA += pa;
        accA.x = fmaf(pa, ha.x, accA.x); accA.y = fmaf(pa, ha.y, accA.y);
        accA.z = fmaf(pa, ha.z, accA.z); accA.w = fmaf(pa, ha.w, accA.w);
    }

    float denom = (dA + dB) + (dC + dD);
    float inv = 1.0f / denom;
    float4 bi = ((const float4*)bias)[lane];
    float4 sum = make_float4((accA.x + accB.x) + (accC.x + accD.x),
                             (accA.y + accB.y) + (accC.y + accD.y),
                             (accA.z + accB.z) + (accC.z + accD.z),
                             (accA.w + accB.w) + (accC.w + accD.w));
    float4 o = make_float4(fmaf(sum.x, inv, bi.x), fmaf(sum.y, inv, bi.y),
                           fmaf(sum.z, inv, bi.z), fmaf(sum.w, inv, bi.w));

    const float RS2 = 0.70710678118654752f;
    float4 f;
    f.x = 0.5f * o.x * (1.0f + erff(o.x * RS2));
    f.y = 0.5f * o.y * (1.0f + erff(o.y * RS2));
    f.z = 0.5f * o.z * (1.0f + erff(o.z * RS2));
    f.w = 0.5f * o.w * (1.0f + erff(o.w * RS2));

    float s1 = f.x + f.y + f.z + f.w;
    float s2 = f.x * f.x + f.y * f.y + f.z * f.z + f.w * f.w;
    #pragma unroll
    for (int off = 16; off >= 1; off >>= 1) {
        s1 += __shfl_xor_sync(0xffffffffu, s1, off);
        s2 += __shfl_xor_sync(0xffffffffu, s2, off);
    }
    float mu  = s1 * (1.0f / 128.0f);
    float var = s2 * (1.0f / 128.0f) - mu * mu;
    float r = rsqrtf(var + LN_EPS);

    float4 gm = ((const float4*)gamma)[lane];
    float4 bt = ((const float4*)beta)[lane];
    float4 xv = ((const float4*)x)[node * 32 + lane];
    float4 res;
    res.x = (f.x - mu) * r * gm.x + bt.x + xv.x;
    res.y = (f.y - mu) * r * gm.y + bt.y + xv.y;
    res.z = (f.z - mu) * r * gm.z + bt.z + xv.z;
    res.w = (f.w - mu) * r * gm.w + bt.w + xv.w;
    ((float4*)out)[node * 32 + lane] = res;
}

// ---------------- launch: gemm(+logits) || CSR-build, join at agg -------
extern "C" void kernel_launch(void* const* d_in, const int* in_sizes, int n_in,
                              void* d_out, int out_size)
{
    const float* x       = (const float*)d_in[0];
    const void*  ei      = d_in[1];
    const float* W       = (const float*)d_in[2];
    const float* att_src = (const float*)d_in[3];
    const float* att_dst = (const float*)d_in[4];
    const float* bias    = (const float*)d_in[5];
    const float* gamma   = (const float*)d_in[6];
    const float* beta    = (const float*)d_in[7];
    float*       out     = (float*)d_out;

    int n = in_sizes[0] / DD;     // 50000
    int E = in_sizes[1] / 2;      // 600000
    int nb = (n + 255) / 256;     // 196
    int ntiles = (n + 63) / 64;   // 782

    const int GEMM_SMEM = (128 * 128 + 64 * 128) * 4;  // 96KB
    static bool s_init = false;
    static cudaStream_t s2;
    static cudaEvent_t evFork, evJoin;
    static int s_sms = 148;
    if (!s_init) {
        cudaFuncSetAttribute(gemm_kernel,
                             cudaFuncAttributeMaxDynamicSharedMemorySize, GEMM_SMEM);
        cudaStreamCreateWithFlags(&s2, cudaStreamNonBlocking);
        cudaEventCreateWithFlags(&evFork, cudaEventDisableTiming);
        cudaEventCreateWithFlags(&evJoin, cudaEventDisableTiming);
        int dev = 0; cudaGetDevice(&dev);
        cudaDeviceGetAttribute(&s_sms, cudaDevAttrMultiProcessorCount, dev);
        s_init = true;
    }

    int gemm_grid = 2 * s_sms;              // 2 resident blocks per SM
    if (gemm_grid > ntiles) gemm_grid = ntiles;

    cudaEventRecord(evFork, 0);
    cudaStreamWaitEvent(s2, evFork, 0);

    // Chain A (default stream): persistent GEMM + attention logits
    gemm_kernel<<<gemm_grid, 256, GEMM_SMEM>>>(x, W, att_src, att_dst, n, ntiles);

    // Chain B (side stream): CSR build
    detect_zero_kernel<<<nb, 256, 0, s2>>>((const int*)ei, E, n);
    hist_kernel<<<(E + 255) / 256, 256, 0, s2>>>(ei, E);
    scan_local_kernel<<<nb, 256, 0, s2>>>(n);
    scan_fixup_kernel<<<nb, 256, 0, s2>>>(n, nb);
    scatter_kernel<<<(E + 255) / 256, 256, 0, s2>>>(ei, E);

    // Join: agg depends on both chains.
    cudaEventRecord(evJoin, s2);
    cudaStreamWaitEvent(0, evJoin, 0);

    agg_ln_kernel<<<(n + 7) / 8, 256>>>(x, bias, gamma, beta, out, n);
}